// round 12
// baseline (speedup 1.0000x reference)
#include <cuda_runtime.h>
#include <cmath>

// Problem shapes (fixed per reference)
#define B_   32
#define S_   4096
#define QD   512
#define KVD  512

// k2 grid: 444 CTAs = 3 per SM on 148 SMs (single wave at occupancy 3).
// First 28 batches get 14 chunks, last 4 batches get 13 chunks. 28*14+4*13=444.
#define NB14     28
#define MAXNC    14

// k1: 16 q-slices of 32, 4 batches per block
#define QSLICES  16
#define QS_LEN   (QD / QSLICES)   // 32
#define BPB      4                // batches per k1 block

// Scratch (device globals; no allocation allowed)
__device__ float g_wqp[QSLICES * B_ * KVD];       // partial W^T q (1 MB)
__device__ float g_wq[B_ * KVD];                  // final W^T q   (64 KB)
__device__ float g_pm[B_ * MAXNC];
__device__ float g_pl[B_ * MAXNC];
__device__ float g_pacc[B_ * MAXNC * KVD];        // ~917 KB

// ---------------------------------------------------------------------------
// Kernel 1: partial wq over a 32-long q-slice for 4 batches at once.
// grid(QSLICES, B/4) = 128 CTAs, 256 threads; thread t owns k = t and t+256.
// Each W element loaded once per block -> W L2 traffic cut 4x vs 1 batch/blk.
// ---------------------------------------------------------------------------
__global__ void __launch_bounds__(256) k1_wq(const float* __restrict__ query,
                                             const float* __restrict__ weight) {
    const int qs = blockIdx.x;
    const int bg = blockIdx.y;        // batch group (4 batches)
    const int t  = threadIdx.x;

    __shared__ float sq[BPB][QS_LEN];
    if (t < BPB * QS_LEN)
        sq[t >> 5][t & 31] = query[(bg * BPB + (t >> 5)) * QD + qs * QS_LEN + (t & 31)];
    __syncthreads();

    const float* Wp = weight + (size_t)(qs * QS_LEN) * KVD + t;
    float s0[BPB], s1[BPB];
#pragma unroll
    for (int j = 0; j < BPB; ++j) { s0[j] = 0.f; s1[j] = 0.f; }

#pragma unroll
    for (int q = 0; q < QS_LEN; ++q) {
        const float w0 = Wp[(size_t)q * KVD];
        const float w1 = Wp[(size_t)q * KVD + 256];
#pragma unroll
        for (int j = 0; j < BPB; ++j) {
            const float qv = sq[j][q];
            s0[j] += qv * w0;
            s1[j] += qv * w1;
        }
    }
#pragma unroll
    for (int j = 0; j < BPB; ++j) {
        float* dst = g_wqp + ((size_t)qs * B_ + bg * BPB + j) * KVD;
        dst[t]       = s0[j];
        dst[t + 256] = s1[j];
    }
}

// ---------------------------------------------------------------------------
// Kernel 1r: reduce the 16 q-slice partials -> g_wq.
// grid(128), 128 threads: block owns a 128-wide k-slice of one batch.
// ---------------------------------------------------------------------------
__global__ void __launch_bounds__(128) k1r_reduce() {
    const int b = blockIdx.x >> 2;
    const int k = (blockIdx.x & 3) * 128 + threadIdx.x;
    float s = 0.f;
#pragma unroll
    for (int qs = 0; qs < QSLICES; ++qs)
        s += g_wqp[((size_t)qs * B_ + b) * KVD + k];
    g_wq[b * KVD + k] = s;
}

// ---------------------------------------------------------------------------
// Kernel 2: fused masked-score + online softmax + weighted sum over a chunk.
// grid(444), 256 threads (8 warps). Warp-per-row; lane owns 16 k-values.
// ---------------------------------------------------------------------------
__global__ void __launch_bounds__(256, 3) k2_fused(const float* __restrict__ kv,
                                                   const int*   __restrict__ mask) {
    const int id  = blockIdx.x;
    int b, c, n;
    if (id < NB14 * 14) { b = id / 14; c = id % 14; n = 14; }
    else { const int r = id - NB14 * 14; b = NB14 + r / 13; c = r % 13; n = 13; }

    const int base  = S_ / n;
    const int rem   = S_ % n;
    const int start = c * base + min(c, rem);
    const int R     = base + (c < rem ? 1 : 0);   // rows in this chunk

    const int tid  = threadIdx.x;
    const int w    = tid >> 5;
    const int lane = tid & 31;

    __shared__ float s_m[8];
    __shared__ float s_l[8];
    __shared__ float s_acc[8][KVD];   // 16 KB

    // wq straight from global (L2 resident, written once by k1r)
    float4 wqr[4];
    {
        const float4* wq4 = (const float4*)(g_wq + b * KVD);
#pragma unroll
        for (int j = 0; j < 4; ++j) wqr[j] = wq4[j * 32 + lane];
    }

    const size_t rowbase = ((size_t)b * S_ + (size_t)start);
    const float4* kv4 = (const float4*)(kv + rowbase * KVD);
    const int*    mb  = mask + rowbase;

    float m = -1e30f, l = 0.f;
    float4 acc[4];
#pragma unroll
    for (int j = 0; j < 4; ++j) acc[j] = make_float4(0.f, 0.f, 0.f, 0.f);

    float4 cur[4], nxt[4];
    int curmask = 0, nxtmask = 0;

    int r = w;
    if (r < R) {
        const float4* rp = kv4 + (size_t)r * (KVD / 4);
#pragma unroll
        for (int j = 0; j < 4; ++j) cur[j] = rp[j * 32 + lane];
        curmask = mb[r];
    }

    while (r < R) {
        const int rn = r + 8;
        if (rn < R) {   // prefetch next row (uniform branch within warp)
            const float4* rp = kv4 + (size_t)rn * (KVD / 4);
#pragma unroll
            for (int j = 0; j < 4; ++j) nxt[j] = rp[j * 32 + lane];
            nxtmask = mb[rn];
        }

        // dot(kv_row, wq)
        float d = 0.f;
#pragma unroll
        for (int j = 0; j < 4; ++j) {
            d += cur[j].x * wqr[j].x;
            d += cur[j].y * wqr[j].y;
            d += cur[j].z * wqr[j].z;
            d += cur[j].w * wqr[j].w;
        }
#pragma unroll
        for (int off = 16; off > 0; off >>= 1)
            d += __shfl_xor_sync(0xFFFFFFFFu, d, off);

        const bool  valid = (curmask != 0);
        const float dv    = valid ? d : -1e30f;
        const float mnew  = fmaxf(m, dv);
        const float alpha = __expf(m - mnew);          // ==1 when m unchanged
        const float p     = valid ? __expf(d - mnew) : 0.f;

        l = l * alpha + p;
#pragma unroll
        for (int j = 0; j < 4; ++j) {
            acc[j].x = acc[j].x * alpha + p * cur[j].x;
            acc[j].y = acc[j].y * alpha + p * cur[j].y;
            acc[j].z = acc[j].z * alpha + p * cur[j].z;
            acc[j].w = acc[j].w * alpha + p * cur[j].w;
        }
        m = mnew;

#pragma unroll
        for (int j = 0; j < 4; ++j) cur[j] = nxt[j];
        curmask = nxtmask;
        r = rn;
    }

    // --- block combine across 8 warps ---
    if (lane == 0) { s_m[w] = m; s_l[w] = l; }
    float4* srow = (float4*)s_acc[w];
#pragma unroll
    for (int j = 0; j < 4; ++j) srow[j * 32 + lane] = acc[j];
    __syncthreads();

    float mblk = -1e30f;
#pragma unroll
    for (int w2 = 0; w2 < 8; ++w2) mblk = fmaxf(mblk, s_m[w2]);
    float f[8];
    float lblk = 0.f;
#pragma unroll
    for (int w2 = 0; w2 < 8; ++w2) {
        f[w2] = __expf(s_m[w2] - mblk);
        lblk += f[w2] * s_l[w2];
    }

    const size_t pbase = ((size_t)b * MAXNC + c) * KVD;
    for (int k = tid; k < KVD; k += 256) {
        float v = 0.f;
#pragma unroll
        for (int w2 = 0; w2 < 8; ++w2) v += f[w2] * s_acc[w2][k];
        g_pacc[pbase + k] = v;
    }
    if (tid == 0) { g_pm[b * MAXNC + c] = mblk; g_pl[b * MAXNC + c] = lblk; }
}

// ---------------------------------------------------------------------------
// Kernel 3: combine chunk partials.
// grid(B*4), 128 threads: block owns a 128-wide k-slice of one batch and
// redundantly recomputes the (cheap) per-batch softmax normalizers.
// ---------------------------------------------------------------------------
__global__ void __launch_bounds__(128) k3_combine(float* __restrict__ out) {
    const int b   = blockIdx.x >> 2;
    const int ks  = (blockIdx.x & 3) * 128;
    const int tid = threadIdx.x;
    const int n   = (b < NB14) ? 14 : 13;

    __shared__ float spm[MAXNC], spl[MAXNC];
    if (tid < n) { spm[tid] = g_pm[b * MAXNC + tid]; spl[tid] = g_pl[b * MAXNC + tid]; }
    __syncthreads();

    float mstar = -1e30f;
    for (int cc = 0; cc < n; ++cc) mstar = fmaxf(mstar, spm[cc]);

    float denom = 0.f, acc = 0.f;
    const int k = ks + tid;
    for (int cc = 0; cc < n; ++cc) {
        const float fc = __expf(spm[cc] - mstar);
        denom += fc * spl[cc];
        acc   += fc * g_pacc[((size_t)b * MAXNC + cc) * KVD + k];
    }
    out[b * KVD + k] = acc / denom;
}

// ---------------------------------------------------------------------------
extern "C" void kernel_launch(void* const* d_in, const int* in_sizes, int n_in,
                              void* d_out, int out_size) {
    const float* query  = (const float*)d_in[0];   // [32, 512]
    const float* kv     = (const float*)d_in[1];   // [32, 4096, 512]
    const int*   mask   = (const int*)  d_in[2];   // [32, 4096]
    const float* weight = (const float*)d_in[3];   // [512, 512]
    float* out = (float*)d_out;                    // [32, 512]

    (void)in_sizes; (void)n_in; (void)out_size;

    k1_wq<<<dim3(QSLICES, B_ / BPB), 256>>>(query, weight);
    k1r_reduce<<<128, 128>>>();
    k2_fused<<<444, 256>>>(kv, mask);
    k3_combine<<<B_ * 4, 128>>>(out);
}

// round 15
// speedup vs baseline: 1.0242x; 1.0242x over previous
#include <cuda_runtime.h>
#include <cmath>

// Problem shapes (fixed per reference)
#define B_   32
#define S_   4096
#define QD   512
#define KVD  512

// k2 grid: 444 CTAs = 3 per SM on 148 SMs (single wave at occupancy 3).
// First 28 batches get 14 chunks, last 4 batches get 13 chunks. 28*14+4*13=444.
#define NB14     28
#define MAXNC    14

// k1: 16 q-slices of 32
#define QSLICES  16
#define QS_LEN   (QD / QSLICES)   // 32

// Scratch (device globals; no allocation allowed)
__device__ float g_wqp[QSLICES * B_ * KVD];       // partial W^T q (1 MB)
__device__ float g_wq[B_ * KVD];                  // final W^T q   (64 KB)
__device__ float g_pm[B_ * MAXNC];
__device__ float g_pl[B_ * MAXNC];
__device__ float g_pacc[B_ * MAXNC * KVD];        // ~917 KB

// ---------------------------------------------------------------------------
// Kernel 1: partial wq over a 32-long q-slice.
// grid(QSLICES, B) = 512 CTAs, 128 threads; thread t owns k-quad t (float4).
// 32 fully-unrolled independent LDG.128 per thread -> high MLP.
// ---------------------------------------------------------------------------
__global__ void __launch_bounds__(128) k1_wq(const float* __restrict__ query,
                                             const float* __restrict__ weight) {
    const int qs = blockIdx.x;
    const int b  = blockIdx.y;
    const int t  = threadIdx.x;   // 0..127 -> k-quad

    __shared__ float sq[QS_LEN];
    if (t < QS_LEN) sq[t] = query[b * QD + qs * QS_LEN + t];
    __syncthreads();

    const float4* W4 = (const float4*)(weight + (size_t)(qs * QS_LEN) * KVD) + t;
    float4 s = make_float4(0.f, 0.f, 0.f, 0.f);
#pragma unroll
    for (int q = 0; q < QS_LEN; ++q) {
        const float4 w = W4[(size_t)q * (KVD / 4)];
        const float qv = sq[q];
        s.x += qv * w.x;
        s.y += qv * w.y;
        s.z += qv * w.z;
        s.w += qv * w.w;
    }
    ((float4*)(g_wqp + ((size_t)qs * B_ + b) * KVD))[t] = s;
}

// ---------------------------------------------------------------------------
// Kernel 1r: reduce the 16 q-slice partials -> g_wq.
// grid(32), 128 threads; thread owns one float4; constant unroll -> MLP 16.
// ---------------------------------------------------------------------------
__global__ void __launch_bounds__(128) k1r_reduce() {
    const int b = blockIdx.x;
    const int t = threadIdx.x;
    float4 s = make_float4(0.f, 0.f, 0.f, 0.f);
#pragma unroll
    for (int qs = 0; qs < QSLICES; ++qs) {
        const float4 v = ((const float4*)(g_wqp + ((size_t)qs * B_ + b) * KVD))[t];
        s.x += v.x; s.y += v.y; s.z += v.z; s.w += v.w;
    }
    ((float4*)(g_wq + b * KVD))[t] = s;
}

// ---------------------------------------------------------------------------
// Kernel 2: fused masked-score + online softmax + weighted sum over a chunk.
// grid(444), 256 threads (8 warps). Warp-per-row; lane owns 16 k-values.
// ---------------------------------------------------------------------------
__global__ void __launch_bounds__(256, 3) k2_fused(const float* __restrict__ kv,
                                                   const int*   __restrict__ mask) {
    const int id  = blockIdx.x;
    int b, c, n;
    if (id < NB14 * 14) { b = id / 14; c = id % 14; n = 14; }
    else { const int r = id - NB14 * 14; b = NB14 + r / 13; c = r % 13; n = 13; }

    const int base  = S_ / n;
    const int rem   = S_ % n;
    const int start = c * base + min(c, rem);
    const int R     = base + (c < rem ? 1 : 0);   // rows in this chunk

    const int tid  = threadIdx.x;
    const int w    = tid >> 5;
    const int lane = tid & 31;

    __shared__ float s_m[8];
    __shared__ float s_l[8];
    __shared__ float s_acc[8][KVD];   // 16 KB

    // wq straight from global (L2 resident, written once by k1r)
    float4 wqr[4];
    {
        const float4* wq4 = (const float4*)(g_wq + b * KVD);
#pragma unroll
        for (int j = 0; j < 4; ++j) wqr[j] = wq4[j * 32 + lane];
    }

    const size_t rowbase = ((size_t)b * S_ + (size_t)start);
    const float4* kv4 = (const float4*)(kv + rowbase * KVD);
    const int*    mb  = mask + rowbase;

    float m = -1e30f, l = 0.f;
    float4 acc[4];
#pragma unroll
    for (int j = 0; j < 4; ++j) acc[j] = make_float4(0.f, 0.f, 0.f, 0.f);

    float4 cur[4], nxt[4];
    int curmask = 0, nxtmask = 0;

    int r = w;
    if (r < R) {
        const float4* rp = kv4 + (size_t)r * (KVD / 4);
#pragma unroll
        for (int j = 0; j < 4; ++j) cur[j] = rp[j * 32 + lane];
        curmask = mb[r];
    }

    while (r < R) {
        const int rn = r + 8;
        if (rn < R) {   // prefetch next row (uniform branch within warp)
            const float4* rp = kv4 + (size_t)rn * (KVD / 4);
#pragma unroll
            for (int j = 0; j < 4; ++j) nxt[j] = rp[j * 32 + lane];
            nxtmask = mb[rn];
        }

        // dot(kv_row, wq)
        float d = 0.f;
#pragma unroll
        for (int j = 0; j < 4; ++j) {
            d += cur[j].x * wqr[j].x;
            d += cur[j].y * wqr[j].y;
            d += cur[j].z * wqr[j].z;
            d += cur[j].w * wqr[j].w;
        }
#pragma unroll
        for (int off = 16; off > 0; off >>= 1)
            d += __shfl_xor_sync(0xFFFFFFFFu, d, off);

        const bool  valid = (curmask != 0);
        const float dv    = valid ? d : -1e30f;
        const float mnew  = fmaxf(m, dv);
        const float alpha = __expf(m - mnew);          // ==1 when m unchanged
        const float p     = valid ? __expf(d - mnew) : 0.f;

        l = l * alpha + p;
#pragma unroll
        for (int j = 0; j < 4; ++j) {
            acc[j].x = acc[j].x * alpha + p * cur[j].x;
            acc[j].y = acc[j].y * alpha + p * cur[j].y;
            acc[j].z = acc[j].z * alpha + p * cur[j].z;
            acc[j].w = acc[j].w * alpha + p * cur[j].w;
        }
        m = mnew;

#pragma unroll
        for (int j = 0; j < 4; ++j) cur[j] = nxt[j];
        curmask = nxtmask;
        r = rn;
    }

    // --- block combine across 8 warps ---
    if (lane == 0) { s_m[w] = m; s_l[w] = l; }
    float4* srow = (float4*)s_acc[w];
#pragma unroll
    for (int j = 0; j < 4; ++j) srow[j * 32 + lane] = acc[j];
    __syncthreads();

    float mblk = -1e30f;
#pragma unroll
    for (int w2 = 0; w2 < 8; ++w2) mblk = fmaxf(mblk, s_m[w2]);
    float f[8];
    float lblk = 0.f;
#pragma unroll
    for (int w2 = 0; w2 < 8; ++w2) {
        f[w2] = __expf(s_m[w2] - mblk);
        lblk += f[w2] * s_l[w2];
    }

    const size_t pbase = ((size_t)b * MAXNC + c) * KVD;
    for (int k = tid; k < KVD; k += 256) {
        float v = 0.f;
#pragma unroll
        for (int w2 = 0; w2 < 8; ++w2) v += f[w2] * s_acc[w2][k];
        g_pacc[pbase + k] = v;
    }
    if (tid == 0) { g_pm[b * MAXNC + c] = mblk; g_pl[b * MAXNC + c] = lblk; }
}

// ---------------------------------------------------------------------------
// Kernel 3: combine chunk partials.  grid(B), 128 threads; thread owns one
// float4.  Loop trip count is a compile-time constant (MAXNC) so it fully
// unrolls -> 14 front-batched LDG.128 (MLP 14) instead of a serial
// load->fma->branch chain.  Missing 14th chunk (n=13) is neutralized by
// spm=-1e30 -> fc=0 (stale g_pacc values are finite, so fc*v == 0).
// ---------------------------------------------------------------------------
__global__ void __launch_bounds__(128) k3_combine(float* __restrict__ out) {
    const int b = blockIdx.x;
    const int t = threadIdx.x;     // quad index 0..127
    const int n = (b < NB14) ? 14 : 13;

    __shared__ float spm[MAXNC], spl[MAXNC];
    if (t < MAXNC) {
        spm[t] = (t < n) ? g_pm[b * MAXNC + t] : -1e30f;
        spl[t] = (t < n) ? g_pl[b * MAXNC + t] : 0.f;
    }
    __syncthreads();

    float mstar = -1e30f;
#pragma unroll
    for (int cc = 0; cc < MAXNC; ++cc) mstar = fmaxf(mstar, spm[cc]);

    float fc[MAXNC];
    float denom = 0.f;
#pragma unroll
    for (int cc = 0; cc < MAXNC; ++cc) {
        fc[cc] = __expf(spm[cc] - mstar);
        denom += fc[cc] * spl[cc];
    }

    const float4* p4 = (const float4*)(g_pacc + (size_t)b * MAXNC * KVD) + t;
    float4 a = make_float4(0.f, 0.f, 0.f, 0.f);
#pragma unroll
    for (int cc = 0; cc < MAXNC; ++cc) {
        const float4 v = p4[(size_t)cc * (KVD / 4)];
        a.x += fc[cc] * v.x;
        a.y += fc[cc] * v.y;
        a.z += fc[cc] * v.z;
        a.w += fc[cc] * v.w;
    }

    const float inv = 1.0f / denom;
    ((float4*)(out + b * KVD))[t] =
        make_float4(a.x * inv, a.y * inv, a.z * inv, a.w * inv);
}

// ---------------------------------------------------------------------------
extern "C" void kernel_launch(void* const* d_in, const int* in_sizes, int n_in,
                              void* d_out, int out_size) {
    const float* query  = (const float*)d_in[0];   // [32, 512]
    const float* kv     = (const float*)d_in[1];   // [32, 4096, 512]
    const int*   mask   = (const int*)  d_in[2];   // [32, 4096]
    const float* weight = (const float*)d_in[3];   // [512, 512]
    float* out = (float*)d_out;                    // [32, 512]

    (void)in_sizes; (void)n_in; (void)out_size;

    k1_wq<<<dim3(QSLICES, B_), 128>>>(query, weight);
    k1r_reduce<<<B_, 128>>>();
    k2_fused<<<444, 256>>>(kv, mask);
    k3_combine<<<B_, 128>>>(out);
}

// round 17
// speedup vs baseline: 1.0733x; 1.0479x over previous
#include <cuda_runtime.h>
#include <cmath>

// Problem shapes (fixed per reference)
#define B_   32
#define S_   4096
#define QD   512
#define KVD  512

// k2 grid: 444 CTAs = 3 per SM on 148 SMs (single wave at occupancy 3).
// First 28 batches get 14 chunks, last 4 batches get 13 chunks. 28*14+4*13=444.
#define NB14     28
#define MAXNC    14

// k1: 16 q-slices of 32
#define QSLICES  16
#define QS_LEN   (QD / QSLICES)   // 32

// Scratch (device globals; no allocation allowed).  16B-aligned: all are
// accessed through float4 casts.
__device__ __align__(16) float g_wqp[QSLICES * B_ * KVD];  // partial W^T q (1 MB)
__device__ float g_pm[B_ * MAXNC];
__device__ float g_pl[B_ * MAXNC];
__device__ __align__(16) float g_pacc[B_ * MAXNC * KVD];   // ~917 KB
__device__ int   g_cnt[B_];                                 // arrival counters (self-reset)

// ---------------------------------------------------------------------------
// Kernel 1: partial wq over a 32-long q-slice.
// grid(QSLICES, B) = 512 CTAs, 128 threads; thread t owns k-quad t (float4).
// 32 fully-unrolled independent LDG.128 per thread -> high MLP.
// ---------------------------------------------------------------------------
__global__ void __launch_bounds__(128) k1_wq(const float* __restrict__ query,
                                             const float* __restrict__ weight) {
    const int qs = blockIdx.x;
    const int b  = blockIdx.y;
    const int t  = threadIdx.x;   // 0..127 -> k-quad

    __shared__ float sq[QS_LEN];
    if (t < QS_LEN) sq[t] = query[b * QD + qs * QS_LEN + t];
    __syncthreads();

    const float4* W4 = (const float4*)(weight + (size_t)(qs * QS_LEN) * KVD) + t;
    float4 s = make_float4(0.f, 0.f, 0.f, 0.f);
#pragma unroll
    for (int q = 0; q < QS_LEN; ++q) {
        const float4 w = W4[(size_t)q * (KVD / 4)];
        const float qv = sq[q];
        s.x += qv * w.x;
        s.y += qv * w.y;
        s.z += qv * w.z;
        s.w += qv * w.w;
    }
    ((float4*)(g_wqp + ((size_t)qs * B_ + b) * KVD))[t] = s;
}

// ---------------------------------------------------------------------------
// Kernel 2: prologue (reduce wq partials) + fused masked-score / online
// softmax / weighted sum over a chunk + last-CTA-per-batch combine epilogue.
// grid(444), 256 threads (8 warps). Warp-per-row; lane owns 16 k-values.
// ---------------------------------------------------------------------------
__global__ void __launch_bounds__(256, 3) k2_fused(const float* __restrict__ kv,
                                                   const int*   __restrict__ mask,
                                                   float*       __restrict__ out) {
    const int id  = blockIdx.x;
    int b, c, n;
    if (id < NB14 * 14) { b = id / 14; c = id % 14; n = 14; }
    else { const int r = id - NB14 * 14; b = NB14 + r / 13; c = r % 13; n = 13; }

    const int base  = S_ / n;
    const int rem   = S_ % n;
    const int start = c * base + min(c, rem);
    const int R     = base + (c < rem ? 1 : 0);   // rows in this chunk

    const int tid  = threadIdx.x;
    const int w    = tid >> 5;
    const int lane = tid & 31;

    // NOTE: s_acc is accessed via float4 casts -> must be 16B aligned.
    // Keep it explicitly aligned and declare scalars AFTER it so shared-memory
    // layout can never knock it off alignment (R16 bug: an int before it did).
    __shared__ __align__(16) float s_acc[8][KVD];   // 16 KB; row 0 doubles as wq staging
    __shared__ float s_m[8];
    __shared__ float s_l[8];
    __shared__ int   s_last;

    // --- prologue: reduce the 16 q-slice partials -> shared -> registers ---
    float* swq = &s_acc[0][0];
    if (tid < 128) {
        float4 s = make_float4(0.f, 0.f, 0.f, 0.f);
#pragma unroll
        for (int qs = 0; qs < QSLICES; ++qs) {
            const float4 v = ((const float4*)(g_wqp + ((size_t)qs * B_ + b) * KVD))[tid];
            s.x += v.x; s.y += v.y; s.z += v.z; s.w += v.w;
        }
        ((float4*)swq)[tid] = s;
    }
    __syncthreads();

    float4 wqr[4];
    {
        const float4* swq4 = (const float4*)swq;
#pragma unroll
        for (int j = 0; j < 4; ++j) wqr[j] = swq4[j * 32 + lane];
    }
    __syncthreads();   // done reading swq; s_acc reusable after the loop

    const size_t rowbase = ((size_t)b * S_ + (size_t)start);
    const float4* kv4 = (const float4*)(kv + rowbase * KVD);
    const int*    mb  = mask + rowbase;

    float m = -1e30f, l = 0.f;
    float4 acc[4];
#pragma unroll
    for (int j = 0; j < 4; ++j) acc[j] = make_float4(0.f, 0.f, 0.f, 0.f);

    float4 cur[4], nxt[4];
    int curmask = 0, nxtmask = 0;

    int r = w;
    if (r < R) {
        const float4* rp = kv4 + (size_t)r * (KVD / 4);
#pragma unroll
        for (int j = 0; j < 4; ++j) cur[j] = rp[j * 32 + lane];
        curmask = mb[r];
    }

    while (r < R) {
        const int rn = r + 8;
        if (rn < R) {   // prefetch next row (uniform branch within warp)
            const float4* rp = kv4 + (size_t)rn * (KVD / 4);
#pragma unroll
            for (int j = 0; j < 4; ++j) nxt[j] = rp[j * 32 + lane];
            nxtmask = mb[rn];
        }

        // dot(kv_row, wq)
        float d = 0.f;
#pragma unroll
        for (int j = 0; j < 4; ++j) {
            d += cur[j].x * wqr[j].x;
            d += cur[j].y * wqr[j].y;
            d += cur[j].z * wqr[j].z;
            d += cur[j].w * wqr[j].w;
        }
#pragma unroll
        for (int off = 16; off > 0; off >>= 1)
            d += __shfl_xor_sync(0xFFFFFFFFu, d, off);

        const bool  valid = (curmask != 0);
        const float dv    = valid ? d : -1e30f;
        const float mnew  = fmaxf(m, dv);
        const float alpha = __expf(m - mnew);          // ==1 when m unchanged
        const float p     = valid ? __expf(d - mnew) : 0.f;

        l = l * alpha + p;
#pragma unroll
        for (int j = 0; j < 4; ++j) {
            acc[j].x = acc[j].x * alpha + p * cur[j].x;
            acc[j].y = acc[j].y * alpha + p * cur[j].y;
            acc[j].z = acc[j].z * alpha + p * cur[j].z;
            acc[j].w = acc[j].w * alpha + p * cur[j].w;
        }
        m = mnew;

#pragma unroll
        for (int j = 0; j < 4; ++j) cur[j] = nxt[j];
        curmask = nxtmask;
        r = rn;
    }

    // --- block combine across 8 warps ---
    if (lane == 0) { s_m[w] = m; s_l[w] = l; }
    float4* srow = (float4*)s_acc[w];
#pragma unroll
    for (int j = 0; j < 4; ++j) srow[j * 32 + lane] = acc[j];
    __syncthreads();

    float mblk = -1e30f;
#pragma unroll
    for (int w2 = 0; w2 < 8; ++w2) mblk = fmaxf(mblk, s_m[w2]);
    float f[8];
    float lblk = 0.f;
#pragma unroll
    for (int w2 = 0; w2 < 8; ++w2) {
        f[w2] = __expf(s_m[w2] - mblk);
        lblk += f[w2] * s_l[w2];
    }

    const size_t pbase = ((size_t)b * MAXNC + c) * KVD;
    for (int k = tid; k < KVD; k += 256) {
        float v = 0.f;
#pragma unroll
        for (int w2 = 0; w2 < 8; ++w2) v += f[w2] * s_acc[w2][k];
        g_pacc[pbase + k] = v;
    }
    if (tid == 0) { g_pm[b * MAXNC + c] = mblk; g_pl[b * MAXNC + c] = lblk; }

    // --- arrival: last CTA of this batch performs the final combine ---
    __threadfence();
    if (tid == 0) {
        const int old = atomicAdd(&g_cnt[b], 1);
        s_last = (old == n - 1);
        if (s_last) g_cnt[b] = 0;   // self-reset for next graph replay
    }
    __syncthreads();
    if (!s_last) return;
    __threadfence();   // acquire side: make peer CTAs' stores visible

    __shared__ float spm[MAXNC], spl[MAXNC];
    if (tid < MAXNC) {
        spm[tid] = (tid < n) ? g_pm[b * MAXNC + tid] : -1e30f;
        spl[tid] = (tid < n) ? g_pl[b * MAXNC + tid] : 0.f;
    }
    __syncthreads();

    if (tid < 128) {
        float mstar = -1e30f;
#pragma unroll
        for (int cc = 0; cc < MAXNC; ++cc) mstar = fmaxf(mstar, spm[cc]);

        float fc[MAXNC];
        float denom = 0.f;
#pragma unroll
        for (int cc = 0; cc < MAXNC; ++cc) {
            fc[cc] = __expf(spm[cc] - mstar);
            denom += fc[cc] * spl[cc];
        }

        const float4* p4 = (const float4*)(g_pacc + (size_t)b * MAXNC * KVD) + tid;
        float4 a = make_float4(0.f, 0.f, 0.f, 0.f);
#pragma unroll
        for (int cc = 0; cc < MAXNC; ++cc) {
            const float4 v = p4[(size_t)cc * (KVD / 4)];
            a.x += fc[cc] * v.x;
            a.y += fc[cc] * v.y;
            a.z += fc[cc] * v.z;
            a.w += fc[cc] * v.w;
        }

        const float inv = 1.0f / denom;
        ((float4*)(out + b * KVD))[tid] =
            make_float4(a.x * inv, a.y * inv, a.z * inv, a.w * inv);
    }
}

// ---------------------------------------------------------------------------
extern "C" void kernel_launch(void* const* d_in, const int* in_sizes, int n_in,
                              void* d_out, int out_size) {
    const float* query  = (const float*)d_in[0];   // [32, 512]
    const float* kv     = (const float*)d_in[1];   // [32, 4096, 512]
    const int*   mask   = (const int*)  d_in[2];   // [32, 4096]
    const float* weight = (const float*)d_in[3];   // [512, 512]
    float* out = (float*)d_out;                    // [32, 512]

    (void)in_sizes; (void)n_in; (void)out_size;

    k1_wq<<<dim3(QSLICES, B_), 128>>>(query, weight);
    k2_fused<<<444, 256>>>(kv, mask, out);
}